// round 1
// baseline (speedup 1.0000x reference)
#include <cuda_runtime.h>

#define NB 8
#define HW 4096
#define CI 256
#define CA 128
#define CO 256
#define BI 64
#define BJ 64
#define QSTR 129
#define SSTR 65
// 1/(1e-8 + sqrt(128))
#define INVS 0.08838834764831843f

// Scratch (allocation-free: __device__ globals)
__device__ float g_q[NB * HW * CA];      // [n][pos][128]
__device__ float g_feat[NB * HW * CO];   // [n][pos][256]
__device__ float g_scale[CO + CA];
__device__ float g_bias[CO + CA];

// ---------------------------------------------------------------------------
// Fold BN into per-channel scale/bias: y = conv*scale + bias, then ReLU.
// Channels [0,256) = reduc (feat), [256,384) = att (q).
// ---------------------------------------------------------------------------
__global__ void prep_kernel(const float* __restrict__ rg, const float* __restrict__ rb,
                            const float* __restrict__ rm, const float* __restrict__ rv,
                            const float* __restrict__ ag, const float* __restrict__ ab,
                            const float* __restrict__ am, const float* __restrict__ av) {
    int o = threadIdx.x;
    if (o < CO) {
        float inv = rg[o] * rsqrtf(rv[o] + 1e-5f);
        g_scale[o] = inv;
        g_bias[o]  = rb[o] - rm[o] * inv;
    } else if (o < CO + CA) {
        int a = o - CO;
        float inv = ag[a] * rsqrtf(av[a] + 1e-5f);
        g_scale[o] = inv;
        g_bias[o]  = ab[a] - am[a] * inv;
    }
}

// ---------------------------------------------------------------------------
// Projection GEMM: out[o][p] = relu(scale[o] * sum_c W[o][c]*x[n][c][p] + bias[o])
// Stored transposed: g_feat[n][p][o] / g_q[n][p][o-256] (position-major rows).
// Block: 64o x 64p tile, 256 threads, 4x4 per thread, K chunks of 16.
// ---------------------------------------------------------------------------
__global__ __launch_bounds__(256) void proj_kernel(const float* __restrict__ x,
                                                   const float* __restrict__ reduc_w,
                                                   const float* __restrict__ att_w) {
    __shared__ float Ws[16][65];
    __shared__ float Xs[16][65];
    const int pb = blockIdx.x * 64;
    const int ob = blockIdx.y * 64;
    const int n  = blockIdx.z;
    const int t  = threadIdx.x;
    const int tx = t & 15, ty = t >> 4;
    const int o0 = ty * 4, p0 = tx * 4;

    const float* W = (ob < CO) ? (reduc_w + ob * CI) : (att_w + (ob - CO) * CI);
    const float* X = x + (n * CI) * HW + pb;

    float acc[4][4];
#pragma unroll
    for (int i = 0; i < 4; i++)
#pragma unroll
        for (int j = 0; j < 4; j++) acc[i][j] = 0.f;

    for (int kb = 0; kb < CI; kb += 16) {
        {   // load Ws[k][o]: each thread grabs float4 along k of one o-row
            int o  = t >> 2;
            int k0 = (t & 3) * 4;
            float4 w4 = *(const float4*)(W + o * CI + kb + k0);
            Ws[k0 + 0][o] = w4.x;
            Ws[k0 + 1][o] = w4.y;
            Ws[k0 + 2][o] = w4.z;
            Ws[k0 + 3][o] = w4.w;
        }
        {   // load Xs[k][p]: coalesced rows of x
            int p  = t & 63;
            int kk = t >> 6;
#pragma unroll
            for (int r = 0; r < 4; r++)
                Xs[kk + 4 * r][p] = X[(kb + kk + 4 * r) * HW + p];
        }
        __syncthreads();
#pragma unroll
        for (int k = 0; k < 16; k++) {
            float a[4], b[4];
#pragma unroll
            for (int i = 0; i < 4; i++) a[i] = Ws[k][o0 + i];
#pragma unroll
            for (int j = 0; j < 4; j++) b[j] = Xs[k][p0 + j];
#pragma unroll
            for (int i = 0; i < 4; i++)
#pragma unroll
                for (int j = 0; j < 4; j++)
                    acc[i][j] = fmaf(a[i], b[j], acc[i][j]);
        }
        __syncthreads();
    }

#pragma unroll
    for (int i = 0; i < 4; i++) {
        int o = ob + o0 + i;
        float sc = g_scale[o], bs = g_bias[o];
#pragma unroll
        for (int j = 0; j < 4; j++) {
            float v = fmaxf(fmaf(acc[i][j], sc, bs), 0.f);
            int p = pb + p0 + j;
            if (o < CO)
                g_feat[(n * HW + p) * CO + o] = v;
            else
                g_q[(n * HW + p) * CA + (o - CO)] = v;
        }
    }
}

// ---------------------------------------------------------------------------
// Flash self-attention (fp32 baseline):
//   S[i][j] = (q_i . q_j) * INVS + (mask_j - 1)*1e8
//   online softmax over j; out[n][c][i] = (sum_j P[i][j] feat[j][c]) / l_i * mask_i
// Block = (n, 64 i-positions), 256 threads.
//   Stage A: 4i x 4j per thread (tx -> i group, tg -> j group)
//   Stage B: 4i x 16c per thread (tx -> i group, tg -> c group)
// ---------------------------------------------------------------------------
__global__ __launch_bounds__(256) void flash_kernel(const float* __restrict__ mask,
                                                    float* __restrict__ out) {
    extern __shared__ float sm[];
    float* qi      = sm;                   // 64 x QSTR
    float* qj      = qi + BI * QSTR;       // 64 x QSTR
    float* fj      = qj + BJ * QSTR;       // 64 x 256
    float* ss      = fj + BJ * CO;         // 64 x SSTR (scores -> P)
    float* alpha_s = ss + BI * SSTR;       // 64
    float* l_s     = alpha_s + BI;         // 64
    float* mj      = l_s + BI;             // 64 additive mask term

    const int n  = blockIdx.y;
    const int ib = blockIdx.x * BI;
    const int t  = threadIdx.x;
    const int tx = t & 15, tg = t >> 4;

    // load q_i tile (padded-stride rows => conflict-free later reads)
    const float* qsrc = g_q + (n * HW + ib) * CA;
    for (int e = t; e < BI * CA; e += 256) {
        int i = e >> 7, k = e & 127;
        qi[i * QSTR + k] = qsrc[e];
    }

    float m_i = -1e30f, l_i = 0.f;
    float acc[16][4];
#pragma unroll
    for (int c = 0; c < 16; c++)
#pragma unroll
        for (int ii = 0; ii < 4; ii++) acc[c][ii] = 0.f;

    const float* maskn = mask + n * HW;

    for (int jb = 0; jb < HW; jb += BJ) {
        // --- stage 0: load tiles ---
        const float* qjs = g_q + (n * HW + jb) * CA;
        for (int e = t; e < BJ * CA; e += 256) {
            int j = e >> 7, k = e & 127;
            qj[j * QSTR + k] = qjs[e];
        }
        const float* fsrc = g_feat + (n * HW + jb) * CO;
        for (int e = t; e < BJ * CO; e += 256) fj[e] = fsrc[e];
        if (t < BJ) mj[t] = (maskn[jb + t] - 1.f) * 1e8f;
        __syncthreads();

        // --- stage A: S = qi . qj ---
        {
            const int i0 = tx * 4, j0 = tg * 4;
            float s[4][4];
#pragma unroll
            for (int ii = 0; ii < 4; ii++)
#pragma unroll
                for (int jj = 0; jj < 4; jj++) s[ii][jj] = 0.f;
#pragma unroll 8
            for (int k = 0; k < CA; k++) {
                float a[4], b[4];
#pragma unroll
                for (int ii = 0; ii < 4; ii++) a[ii] = qi[(i0 + ii) * QSTR + k];
#pragma unroll
                for (int jj = 0; jj < 4; jj++) b[jj] = qj[(j0 + jj) * QSTR + k];
#pragma unroll
                for (int ii = 0; ii < 4; ii++)
#pragma unroll
                    for (int jj = 0; jj < 4; jj++)
                        s[ii][jj] = fmaf(a[ii], b[jj], s[ii][jj]);
            }
#pragma unroll
            for (int ii = 0; ii < 4; ii++)
#pragma unroll
                for (int jj = 0; jj < 4; jj++)
                    ss[(i0 + ii) * SSTR + j0 + jj] = fmaf(s[ii][jj], INVS, mj[j0 + jj]);
        }
        __syncthreads();

        // --- online softmax (one row per thread, threads 0..63) ---
        if (t < BI) {
            float* row = ss + t * SSTR;
            float mt = row[0];
#pragma unroll 8
            for (int j = 1; j < BJ; j++) mt = fmaxf(mt, row[j]);
            float mnew  = fmaxf(m_i, mt);
            float alpha = __expf(m_i - mnew);
            float lsum  = 0.f;
#pragma unroll 8
            for (int j = 0; j < BJ; j++) {
                float p = __expf(row[j] - mnew);
                row[j] = p;
                lsum += p;
            }
            l_i = fmaf(l_i, alpha, lsum);
            m_i = mnew;
            alpha_s[t] = alpha;
        }
        __syncthreads();

        // --- stage B: acc = acc*alpha + P @ feat ---
        {
            const int i0 = tx * 4, c0 = tg * 16;
            float al[4];
#pragma unroll
            for (int ii = 0; ii < 4; ii++) al[ii] = alpha_s[i0 + ii];
#pragma unroll
            for (int c = 0; c < 16; c++)
#pragma unroll
                for (int ii = 0; ii < 4; ii++) acc[c][ii] *= al[ii];

#pragma unroll 2
            for (int j = 0; j < BJ; j++) {
                float p[4];
#pragma unroll
                for (int ii = 0; ii < 4; ii++) p[ii] = ss[(i0 + ii) * SSTR + j];
                const float4* fr = (const float4*)(fj + j * CO + c0);
#pragma unroll
                for (int q = 0; q < 4; q++) {
                    float4 f = fr[q];
#pragma unroll
                    for (int ii = 0; ii < 4; ii++) {
                        acc[4 * q + 0][ii] = fmaf(p[ii], f.x, acc[4 * q + 0][ii]);
                        acc[4 * q + 1][ii] = fmaf(p[ii], f.y, acc[4 * q + 1][ii]);
                        acc[4 * q + 2][ii] = fmaf(p[ii], f.z, acc[4 * q + 2][ii]);
                        acc[4 * q + 3][ii] = fmaf(p[ii], f.w, acc[4 * q + 3][ii]);
                    }
                }
            }
        }
        __syncthreads();
    }

    if (t < BI) l_s[t] = l_i;
    __syncthreads();

    // epilogue: normalize, apply output mask, write out[n][c][i] (float4 along i)
    {
        const int i0 = tx * 4, c0 = tg * 16;
        float rl[4], mk[4];
#pragma unroll
        for (int ii = 0; ii < 4; ii++) {
            rl[ii] = 1.f / l_s[i0 + ii];
            mk[ii] = maskn[ib + i0 + ii];
        }
#pragma unroll
        for (int c = 0; c < 16; c++) {
            float4 v;
            v.x = acc[c][0] * rl[0] * mk[0];
            v.y = acc[c][1] * rl[1] * mk[1];
            v.z = acc[c][2] * rl[2] * mk[2];
            v.w = acc[c][3] * rl[3] * mk[3];
            *(float4*)(out + (n * CO + (c0 + c)) * HW + ib + i0) = v;
        }
    }
}

// ---------------------------------------------------------------------------
extern "C" void kernel_launch(void* const* d_in, const int* in_sizes, int n_in,
                              void* d_out, int out_size) {
    const float* x           = (const float*)d_in[0];
    const float* mask        = (const float*)d_in[1];
    const float* reduc_w     = (const float*)d_in[2];
    const float* reduc_gamma = (const float*)d_in[3];
    const float* reduc_beta  = (const float*)d_in[4];
    const float* reduc_mean  = (const float*)d_in[5];
    const float* reduc_var   = (const float*)d_in[6];
    const float* att_w       = (const float*)d_in[7];
    const float* att_gamma   = (const float*)d_in[8];
    const float* att_beta    = (const float*)d_in[9];
    const float* att_mean    = (const float*)d_in[10];
    const float* att_var     = (const float*)d_in[11];
    float* out = (float*)d_out;

    prep_kernel<<<1, CO + CA>>>(reduc_gamma, reduc_beta, reduc_mean, reduc_var,
                                att_gamma, att_beta, att_mean, att_var);

    dim3 gproj(HW / 64, (CO + CA) / 64, NB);
    proj_kernel<<<gproj, 256>>>(x, reduc_w, att_w);

    int smem_bytes = (2 * BI * QSTR + BJ * CO + BI * SSTR + 3 * BI) * (int)sizeof(float);
    cudaFuncSetAttribute(flash_kernel, cudaFuncAttributeMaxDynamicSharedMemorySize, smem_bytes);
    dim3 gfl(HW / BI, NB);
    flash_kernel<<<gfl, 256, smem_bytes>>>(mask, out);
}